// round 2
// baseline (speedup 1.0000x reference)
#include <cuda_runtime.h>

// ---------------- scratch (device globals; no runtime alloc) ----------------
__device__ float g_x1[4*8*128*128];
__device__ float g_x2[4*16*64*64];
__device__ float g_x3[4*32*32*32];
__device__ float g_x4[4*64*16*16];
__device__ float g_splat[4*64*256];
__device__ float g_l3[4*64*256];
__device__ float g_cvec[4*64];
__device__ float g_grid[4*12*8*256];   // [b][cc 12][lb 8][y 16][x 16]

// ============== conv1: fused bilinear 1024->256 downsample + 3x3 s2 conv ======
// low-res "input" computed on the fly: low(ci,iy,ix) = mean of image pixels
// (4iy+1,4ix+1),(4iy+1,4ix+2),(4iy+2,4ix+1),(4iy+2,4ix+2)
__global__ void __launch_bounds__(256) k_conv1(const float* __restrict__ im,
        const float* __restrict__ w, const float* __restrict__ bias,
        float* __restrict__ out) {
    constexpr int TILE = 8, IT = 17, NT = 16;   // OHW=128, low IHW=256
    constexpr int CIP = 4, CO = 8;
    constexpr int TPC = 32, OPT = 2;            // 64*8/256
    __shared__ float s_in[IT*IT*CIP];
    int bb = blockIdx.y;
    int tile = blockIdx.x;
    int ty0 = (tile/NT)*TILE, tx0 = (tile%NT)*TILE;
    int t = threadIdx.x;
    const float* imb = im + (size_t)bb * 3 * 1048576;
    for (int ci = 0; ci < 4; ci++) {
        for (int i = t; i < IT*IT; i += 256) {
            int iy = 2*ty0 - 1 + i/IT;
            int ix = 2*tx0 - 1 + i%IT;
            float v = 0.f;
            if (ci < 3 && iy >= 0 && iy < 256 && ix >= 0 && ix < 256) {
                const float* p = imb + (size_t)ci*1048576 + (size_t)(4*iy+1)*1024 + (4*ix+1);
                v = 0.25f*(p[0] + p[1] + p[1024] + p[1025]);
            }
            s_in[i*CIP + ci] = v;
        }
    }
    __syncthreads();
    int co = t / TPC;
    int pbase = t % TPC;
    float acc[OPT];
    #pragma unroll
    for (int k = 0; k < OPT; k++) acc[k] = bias[co];
    const float* wc = w + co*3*9;
    float4 wk[9];
    #pragma unroll
    for (int k = 0; k < 9; k++) {
        wk[k].x = wc[0*9+k]; wk[k].y = wc[1*9+k]; wk[k].z = wc[2*9+k]; wk[k].w = 0.f;
    }
    #pragma unroll
    for (int k = 0; k < OPT; k++) {
        int p = pbase + k*TPC;
        int py = p/TILE, px = p%TILE;
        #pragma unroll
        for (int ky = 0; ky < 3; ky++)
        #pragma unroll
        for (int kx = 0; kx < 3; kx++) {
            float4 v = *(const float4*)&s_in[((2*py+ky)*IT + 2*px+kx)*CIP];
            float4 wv = wk[ky*3+kx];
            acc[k] += v.x*wv.x + v.y*wv.y + v.z*wv.z;
        }
    }
    float* outb = out + (size_t)bb*CO*128*128;
    #pragma unroll
    for (int k = 0; k < OPT; k++) {
        int p = pbase + k*TPC;
        outb[(size_t)co*16384 + (size_t)(ty0+p/TILE)*128 + tx0 + p%TILE] = fmaxf(acc[k], 0.f);
    }
}

// ============== generic 3x3 stride-2 conv, pad 1, relu (smem tile, NCHW) =====
template<int CI, int CO, int IHW, int OHW, int TILE>
__global__ void __launch_bounds__(256) k_conv(const float* __restrict__ in,
        const float* __restrict__ w, const float* __restrict__ bias,
        float* __restrict__ out) {
    constexpr int IT = 2*TILE+1;
    constexpr int NT = OHW/TILE;
    constexpr int POS = TILE*TILE;
    constexpr int TPC = 256/CO;
    constexpr int OPT = POS/TPC;
    __shared__ float s_in[IT*IT*CI];
    int bb = blockIdx.y;
    int tile = blockIdx.x;
    int ty0 = (tile/NT)*TILE, tx0 = (tile%NT)*TILE;
    int t = threadIdx.x;
    const float* inb = in + (size_t)bb*CI*IHW*IHW;
    for (int ci = 0; ci < CI; ci++) {
        for (int i = t; i < IT*IT; i += 256) {
            int iy = 2*ty0 - 1 + i/IT;
            int ix = 2*tx0 - 1 + i%IT;
            float v = 0.f;
            if (iy >= 0 && iy < IHW && ix >= 0 && ix < IHW)
                v = inb[(size_t)ci*IHW*IHW + (size_t)iy*IHW + ix];
            s_in[i*CI + ci] = v;
        }
    }
    __syncthreads();
    int co = t / TPC;
    int pbase = t % TPC;
    float acc[OPT];
    #pragma unroll
    for (int k = 0; k < OPT; k++) acc[k] = bias[co];
    const float* wc = w + co*CI*9;
    #pragma unroll 1
    for (int c0 = 0; c0 < CI; c0 += 4) {
        float4 wk[9];
        #pragma unroll
        for (int k = 0; k < 9; k++) {
            wk[k].x = wc[(c0+0)*9+k];
            wk[k].y = wc[(c0+1)*9+k];
            wk[k].z = wc[(c0+2)*9+k];
            wk[k].w = wc[(c0+3)*9+k];
        }
        #pragma unroll
        for (int k = 0; k < OPT; k++) {
            int p = pbase + k*TPC;
            int py = p/TILE, px = p%TILE;
            #pragma unroll
            for (int ky = 0; ky < 3; ky++)
            #pragma unroll
            for (int kx = 0; kx < 3; kx++) {
                float4 v = *(const float4*)&s_in[((2*py+ky)*IT + 2*px+kx)*CI + c0];
                float4 wv = wk[ky*3+kx];
                acc[k] += v.x*wv.x + v.y*wv.y + v.z*wv.z + v.w*wv.w;
            }
        }
    }
    float* outb = out + (size_t)bb*CO*OHW*OHW;
    #pragma unroll
    for (int k = 0; k < OPT; k++) {
        int p = pbase + k*TPC;
        outb[(size_t)co*OHW*OHW + (size_t)(ty0+p/TILE)*OHW + tx0 + p%TILE] = fmaxf(acc[k], 0.f);
    }
}

// ============== fused splat + local path (3 pw layers), 8 positions/block ====
__global__ void __launch_bounds__(256) k_mid(
        const float* __restrict__ spw, const float* __restrict__ spb,
        const float* __restrict__ val,
        const float* __restrict__ lw1, const float* __restrict__ lb1,
        const float* __restrict__ lw2, const float* __restrict__ lb2,
        const float* __restrict__ lw3, const float* __restrict__ lb3) {
    __shared__ float A[128*8], Bf[128*8];
    int bb = blockIdx.y;
    int pos0 = blockIdx.x * 8;
    int t = threadIdx.x;
    const float* x4 = g_x4 + bb*64*256;
    // splat (no relu) -> A + g_splat
    for (int o = t; o < 512; o += 256) {
        int ch = o >> 3, p = o & 7;
        float acc = spb[ch] + val[bb];
        const float* wr = spw + ch*64;
        #pragma unroll 8
        for (int i = 0; i < 64; i++) acc = fmaf(wr[i], x4[i*256 + pos0 + p], acc);
        A[ch*8 + p] = acc;
        g_splat[(bb*64 + ch)*256 + pos0 + p] = acc;
    }
    __syncthreads();
    // l1: 64 -> 128
    for (int o = t; o < 1024; o += 256) {
        int ch = o >> 3, p = o & 7;
        float acc = lb1[ch];
        const float* wr = lw1 + ch*64;
        #pragma unroll 8
        for (int i = 0; i < 64; i++) acc = fmaf(wr[i], A[i*8 + p], acc);
        Bf[ch*8 + p] = fmaxf(acc, 0.f);
    }
    __syncthreads();
    // l2: 128 -> 128
    for (int o = t; o < 1024; o += 256) {
        int ch = o >> 3, p = o & 7;
        float acc = lb2[ch];
        const float* wr = lw2 + ch*128;
        #pragma unroll 8
        for (int i = 0; i < 128; i++) acc = fmaf(wr[i], Bf[i*8 + p], acc);
        A[ch*8 + p] = fmaxf(acc, 0.f);
    }
    __syncthreads();
    // l3: 128 -> 64 -> g_l3
    for (int o = t; o < 512; o += 256) {
        int ch = o >> 3, p = o & 7;
        float acc = lb3[ch];
        const float* wr = lw3 + ch*128;
        #pragma unroll 8
        for (int i = 0; i < 128; i++) acc = fmaf(wr[i], A[i*8 + p], acc);
        g_l3[(bb*64 + ch)*256 + pos0 + p] = fmaxf(acc, 0.f);
    }
}

// ---------------- global path: strided pw -> pool -> fc1 -> fc2 --------------
__global__ void k_global(const float* __restrict__ cw, const float* __restrict__ cb,
                         const float* __restrict__ fw1, const float* __restrict__ fb1,
                         const float* __restrict__ fw2, const float* __restrict__ fb2) {
    int bb = blockIdx.x;
    int t = threadIdx.x;  // 64 threads
    __shared__ float c4[4][64];
    __shared__ float cp[64];
    __shared__ float f1[64];
    const float* sp = g_splat + bb * 64 * 256;
    int gy = t >> 3, gx = t & 7;
    int pos = (2*gy)*16 + 2*gx;
    for (int oc = 0; oc < 4; oc++) {
        float acc = cb[oc];
        for (int i = 0; i < 64; i++) acc = fmaf(cw[oc*64+i], sp[i*256+pos], acc);
        c4[oc][t] = fmaxf(acc, 0.f);
    }
    __syncthreads();
    {
        int oc = t >> 4, py = (t >> 2) & 3, px = t & 3;
        cp[t] = 0.25f * (c4[oc][(2*py)*8 + 2*px]   + c4[oc][(2*py)*8 + 2*px+1] +
                         c4[oc][(2*py+1)*8 + 2*px] + c4[oc][(2*py+1)*8 + 2*px+1]);
    }
    __syncthreads();
    float acc = fb1[t];
    for (int i = 0; i < 64; i++) acc = fmaf(fw1[t*64+i], cp[i], acc);
    f1[t] = fmaxf(acc, 0.f);
    __syncthreads();
    acc = fb2[t];
    for (int i = 0; i < 64; i++) acc = fmaf(fw2[t*64+i], f1[i], acc);
    g_cvec[bb*64 + t] = fmaxf(acc, 0.f);
}

// ---------------- fused = relu(c + loc); coeff = pw 64->96; write grid -------
__global__ void k_coeff(const float* __restrict__ gw, const float* __restrict__ gb) {
    int tile = blockIdx.x;
    int bb = blockIdx.y;
    int t = threadIdx.x;
    __shared__ float fused[64][17];
    const float* l3 = g_l3 + bb * 64 * 256;
    const float* cv = g_cvec + bb * 64;
    for (int k = t; k < 1024; k += 256) {
        int ch = k >> 4, p = k & 15;
        fused[ch][p] = fmaxf(cv[ch] + l3[ch*256 + tile*16 + p], 0.f);
    }
    __syncthreads();
    for (int k = t; k < 1536; k += 256) {
        int och = k >> 4, p = k & 15;
        float acc = gb[och];
        const float* wr = gw + och * 64;
        #pragma unroll 8
        for (int i = 0; i < 64; i++) acc = fmaf(wr[i], fused[i][p], acc);
        int lb = och / 12, cc = och % 12;
        g_grid[((bb*12 + cc)*8 + lb)*256 + tile*16 + p] = acc;
    }
}

// ============== fused guide + bilateral slice =================================
// 64x64 pixel tile. sg: 3x3 xy-cells * 8z * 12ch. Per row-group (4 groups of
// 64 threads), a y-interpolated table gy[3 xcells][8 z][12 ch] halves the taps.
// PWL guide via prefix sums + branchless binary search (shifts sorted).
__global__ void __launch_bounds__(256) k_slice(
        const float* __restrict__ im,
        const float* __restrict__ ccm_w, const float* __restrict__ ccm_b,
        const float* __restrict__ shifts, const float* __restrict__ slopes,
        const float* __restrict__ prw, const float* __restrict__ prb,
        float* __restrict__ out) {
    int bx = blockIdx.x, by = blockIdx.y, bb = blockIdx.z;
    __shared__ float sg[864];               // [cell(j*3+k)][z][c12]
    __shared__ float gy[4*72*4];            // [grp][cellx3][z8][c12] as float4*72
    __shared__ float s_ccm[9], s_ccmb[3], s_prw[3], s_prb[1];
    __shared__ float s_sh[48];              // sorted per channel
    __shared__ float s_cs[3][17], s_csh[3][17];
    int t = threadIdx.x;

    const float* gr = g_grid + (size_t)bb * 12 * 8 * 256;
    for (int k = t; k < 864; k += 256) {
        int c = k % 12;
        int z = (k / 12) % 8;
        int cell = k / 96;
        int j = cell / 3, kx = cell % 3;
        int yi = min(max(by - 1 + j, 0), 15);
        int xi = min(max(bx - 1 + kx, 0), 15);
        sg[k] = gr[(c*8 + z)*256 + yi*16 + xi];
    }
    if (t < 9)               s_ccm[t] = ccm_w[t];
    if (t >= 16 && t < 19)   s_ccmb[t-16] = ccm_b[t-16];
    if (t >= 32 && t < 80)   s_sh[t-32] = shifts[t-32];
    if (t >= 96 && t < 99)   s_prw[t-96] = prw[t-96];
    if (t == 102)            s_prb[0] = prb[0];
    if (t >= 104 && t < 107) {     // prefix sums for channel t-104
        int c = t - 104;
        float cs = 0.f, csh = 0.f;
        s_cs[c][0] = 0.f; s_csh[c][0] = 0.f;
        #pragma unroll
        for (int k = 0; k < 16; k++) {
            float s = slopes[c*16+k], h = shifts[c*16+k];
            cs += s; csh += s*h;
            s_cs[c][k+1] = cs; s_csh[c][k+1] = csh;
        }
    }
    __syncthreads();

    int g = t >> 6;                 // row group 0..3
    int lx = t & 63;
    int x = bx*64 + lx;
    float cxv = ((float)x + 0.5f) * (1.0f/64.0f) - 0.5f;
    float wx = cxv - floorf(cxv);
    int k0 = (int)floorf(cxv) - (bx - 1);     // 0 or 1
    const float* imb = im + (size_t)bb * 3 * 1048576;
    float* outb = out + (size_t)bb * 3 * 1048576;

    for (int r = 0; r < 16; r++) {
        int y = by*64 + g + 4*r;
        float cyv = ((float)y + 0.5f) * (1.0f/64.0f) - 0.5f;
        float wy = cyv - floorf(cyv);
        int j0 = (int)floorf(cyv) - (by - 1);  // 0 or 1

        // build y-interp table for this group (72 float4 entries)
        for (int e = lx; e < 72; e += 64) {
            int cellx = e / 24;
            int z = (e / 3) % 8;
            int v = e % 3;
            float4 a = ((const float4*)sg)[((j0*3 + cellx)*8 + z)*3 + v];
            float4 b4 = ((const float4*)sg)[(((j0+1)*3 + cellx)*8 + z)*3 + v];
            float4 res;
            res.x = fmaf(wy, b4.x - a.x, a.x);
            res.y = fmaf(wy, b4.y - a.y, a.y);
            res.z = fmaf(wy, b4.z - a.z, a.z);
            res.w = fmaf(wy, b4.w - a.w, a.w);
            ((float4*)gy)[g*72 + e] = res;
        }
        asm volatile("bar.sync %0, %1;" :: "r"(g+1), "r"(64) : "memory");

        size_t poff = (size_t)y * 1024 + x;
        float i0 = imb[poff];
        float i1 = imb[poff + 1048576];
        float i2 = imb[poff + 2097152];

        // guide
        float q0 = s_ccmb[0] + s_ccm[0]*i0 + s_ccm[1]*i1 + s_ccm[2]*i2;
        float q1 = s_ccmb[1] + s_ccm[3]*i0 + s_ccm[4]*i1 + s_ccm[5]*i2;
        float q2 = s_ccmb[2] + s_ccm[6]*i0 + s_ccm[7]*i1 + s_ccm[8]*i2;
        float tt[3];
        float qv[3] = {q0, q1, q2};
        #pragma unroll
        for (int c = 0; c < 3; c++) {
            const float* H = &s_sh[c*16];
            float gv = qv[c];
            int p = (gv > H[7]) ? 8 : 0;
            p += (gv > H[p+3]) ? 4 : 0;
            p += (gv > H[p+1]) ? 2 : 0;
            p += (gv > H[p])   ? 1 : 0;
            p += (gv > H[p])   ? 1 : 0;
            tt[c] = fmaf(gv, s_cs[c][p], -s_csh[c][p]);
        }
        float gg = s_prb[0] + s_prw[0]*tt[0] + s_prw[1]*tt[1] + s_prw[2]*tt[2];
        float guide = fminf(fmaxf(gg, 0.f), 1.f);

        float cz = guide * 8.0f - 0.5f;
        float z0f = floorf(cz);
        float wz = cz - z0f;
        int z0 = (int)z0f;
        int zi0 = min(max(z0, 0), 7);
        int zi1 = min(max(z0 + 1, 0), 7);

        float w00 = (1.f-wx)*(1.f-wz), w01 = (1.f-wx)*wz;
        float w10 = wx*(1.f-wz),       w11 = wx*wz;

        const float4* T = (const float4*)gy;
        int bA = (g*3 + k0)*8;
        int bB = bA + 8;
        int iA0 = (bA + zi0)*3, iA1 = (bA + zi1)*3;
        int iB0 = (bB + zi0)*3, iB1 = (bB + zi1)*3;

        float a0=0,a1=0,a2=0,a3=0,a4=0,a5=0,a6=0,a7=0,a8=0,a9=0,a10=0,a11=0;
        {
            float4 v0 = T[iA0], v1 = T[iA1], v2 = T[iB0], v3 = T[iB1];
            a0 = w00*v0.x + w01*v1.x + w10*v2.x + w11*v3.x;
            a1 = w00*v0.y + w01*v1.y + w10*v2.y + w11*v3.y;
            a2 = w00*v0.z + w01*v1.z + w10*v2.z + w11*v3.z;
            a3 = w00*v0.w + w01*v1.w + w10*v2.w + w11*v3.w;
        }
        {
            float4 v0 = T[iA0+1], v1 = T[iA1+1], v2 = T[iB0+1], v3 = T[iB1+1];
            a4 = w00*v0.x + w01*v1.x + w10*v2.x + w11*v3.x;
            a5 = w00*v0.y + w01*v1.y + w10*v2.y + w11*v3.y;
            a6 = w00*v0.z + w01*v1.z + w10*v2.z + w11*v3.z;
            a7 = w00*v0.w + w01*v1.w + w10*v2.w + w11*v3.w;
        }
        {
            float4 v0 = T[iA0+2], v1 = T[iA1+2], v2 = T[iB0+2], v3 = T[iB1+2];
            a8  = w00*v0.x + w01*v1.x + w10*v2.x + w11*v3.x;
            a9  = w00*v0.y + w01*v1.y + w10*v2.y + w11*v3.y;
            a10 = w00*v0.z + w01*v1.z + w10*v2.z + w11*v3.z;
            a11 = w00*v0.w + w01*v1.w + w10*v2.w + w11*v3.w;
        }
        outb[poff]           = fmaf(a0, i0, fmaf(a1, i1, fmaf(a2,  i2, a3)));
        outb[poff + 1048576] = fmaf(a4, i0, fmaf(a5, i1, fmaf(a6,  i2, a7)));
        outb[poff + 2097152] = fmaf(a8, i0, fmaf(a9, i1, fmaf(a10, i2, a11)));

        asm volatile("bar.sync %0, %1;" :: "r"(g+1), "r"(64) : "memory");
    }
}

// ---------------- launcher ---------------------------------------------------
extern "C" void kernel_launch(void* const* d_in, const int* in_sizes, int n_in,
                              void* d_out, int out_size) {
    const float* image = (const float*)d_in[0];
    const float* val   = (const float*)d_in[1];
    const float* sw0 = (const float*)d_in[2];  const float* sb0 = (const float*)d_in[3];
    const float* sw1 = (const float*)d_in[4];  const float* sb1 = (const float*)d_in[5];
    const float* sw2 = (const float*)d_in[6];  const float* sb2 = (const float*)d_in[7];
    const float* sw3 = (const float*)d_in[8];  const float* sb3 = (const float*)d_in[9];
    const float* spw = (const float*)d_in[10]; const float* spb = (const float*)d_in[11];
    const float* lw1 = (const float*)d_in[12]; const float* lb1 = (const float*)d_in[13];
    const float* lw2 = (const float*)d_in[14]; const float* lb2 = (const float*)d_in[15];
    const float* lw3 = (const float*)d_in[16]; const float* lb3 = (const float*)d_in[17];
    const float* cw  = (const float*)d_in[18]; const float* cb  = (const float*)d_in[19];
    const float* fw1 = (const float*)d_in[20]; const float* fb1 = (const float*)d_in[21];
    const float* fw2 = (const float*)d_in[22]; const float* fb2 = (const float*)d_in[23];
    const float* gw  = (const float*)d_in[24]; const float* gb  = (const float*)d_in[25];
    const float* ccm_w = (const float*)d_in[26]; const float* ccm_b = (const float*)d_in[27];
    const float* shifts = (const float*)d_in[28];
    const float* slopes = (const float*)d_in[29];
    const float* prw = (const float*)d_in[30]; const float* prb = (const float*)d_in[31];
    float* out = (float*)d_out;

    float *p_x1, *p_x2, *p_x3, *p_x4;
    cudaGetSymbolAddress((void**)&p_x1, g_x1);
    cudaGetSymbolAddress((void**)&p_x2, g_x2);
    cudaGetSymbolAddress((void**)&p_x3, g_x3);
    cudaGetSymbolAddress((void**)&p_x4, g_x4);

    k_conv1<<<dim3(256, 4), 256>>>(image, sw0, sb0, p_x1);
    k_conv<8, 16, 128, 64, 8><<<dim3(64, 4), 256>>>(p_x1, sw1, sb1, p_x2);
    k_conv<16, 32, 64, 32, 4><<<dim3(64, 4), 256>>>(p_x2, sw2, sb2, p_x3);
    k_conv<32, 64, 32, 16, 2><<<dim3(64, 4), 256>>>(p_x3, sw3, sb3, p_x4);
    k_mid<<<dim3(32, 4), 256>>>(spw, spb, val, lw1, lb1, lw2, lb2, lw3, lb3);
    k_global<<<4, 64>>>(cw, cb, fw1, fb1, fw2, fb2);
    k_coeff<<<dim3(16, 4), 256>>>(gw, gb);
    k_slice<<<dim3(16, 16, 4), 256>>>(image, ccm_w, ccm_b, shifts, slopes, prw, prb, out);
}

// round 4
// speedup vs baseline: 1.0165x; 1.0165x over previous
#include <cuda_runtime.h>

// ---------------- scratch (device globals; no runtime alloc) ----------------
__device__ float g_x1[4*8*128*128];
__device__ float g_x2[4*16*64*64];
__device__ float g_x3[4*32*32*32];
__device__ float g_x4[4*64*16*16];
__device__ float g_splat[4*64*256];
__device__ float g_l3[4*64*256];
__device__ float g_cvec[4*64];
__device__ float g_grid[4*12*8*256];   // [b][cc 12][lb 8][y 16][x 16]
__device__ unsigned int g_barc = 0;

// monotonic grid barrier for k_net (64 blocks, all co-resident)
__device__ __forceinline__ void gbar64() {
    __syncthreads();
    if (threadIdx.x == 0) {
        __threadfence();
        unsigned int old = atomicAdd(&g_barc, 1u);
        unsigned int target = (old / 64u + 1u) * 64u;
        while (*((volatile unsigned int*)&g_barc) < target) __nanosleep(20);
        __threadfence();
    }
    __syncthreads();
}

// ============== generic 3x3 stride-2 conv (smem tile [pos][ci], padded) ======
template<int CI, int CIP, int COG, int CO_TOTAL, int IHW, int OHW, int TILE>
__device__ __forceinline__ void conv_run(const float* __restrict__ in,
        const float* __restrict__ w, const float* __restrict__ bias,
        float* __restrict__ out, float* s_in, int bb, int tile, int cog) {
    constexpr int IT = 2*TILE+1;
    constexpr int NT = OHW/TILE;
    constexpr int POS = TILE*TILE;
    constexpr int TPC = 256/COG;
    constexpr int OPT = POS/TPC;
    int ty0 = (tile/NT)*TILE, tx0 = (tile%NT)*TILE;
    int t = threadIdx.x;
    const float* inb = in + (size_t)bb*CI*IHW*IHW;
    for (int k = t; k < IT*IT*CI; k += 256) {
        int ci = k / (IT*IT);
        int i  = k % (IT*IT);
        int iy = 2*ty0 - 1 + i/IT;
        int ix = 2*tx0 - 1 + i%IT;
        float v = 0.f;
        if (iy >= 0 && iy < IHW && ix >= 0 && ix < IHW)
            v = __ldg(&inb[(size_t)ci*IHW*IHW + (size_t)iy*IHW + ix]);
        s_in[i*CIP + ci] = v;
    }
    __syncthreads();
    int co = cog*COG + t/TPC;
    int pbase = t % TPC;
    float acc[OPT];
    #pragma unroll
    for (int k = 0; k < OPT; k++) acc[k] = bias[co];
    const float* wc = w + co*CI*9;
    #pragma unroll 1
    for (int c0 = 0; c0 < CI; c0 += 4) {
        float4 wk[9];
        #pragma unroll
        for (int k = 0; k < 9; k++) {
            wk[k].x = wc[(c0+0)*9+k];
            wk[k].y = wc[(c0+1)*9+k];
            wk[k].z = wc[(c0+2)*9+k];
            wk[k].w = wc[(c0+3)*9+k];
        }
        #pragma unroll
        for (int k = 0; k < OPT; k++) {
            int p = pbase + k*TPC;
            int py = p/TILE, px = p%TILE;
            #pragma unroll
            for (int ky = 0; ky < 3; ky++)
            #pragma unroll
            for (int kx = 0; kx < 3; kx++) {
                float4 v = *(const float4*)&s_in[((2*py+ky)*IT + 2*px+kx)*CIP + c0];
                float4 wv = wk[ky*3+kx];
                acc[k] += v.x*wv.x + v.y*wv.y + v.z*wv.z + v.w*wv.w;
            }
        }
    }
    float* outb = out + (size_t)bb*CO_TOTAL*OHW*OHW;
    #pragma unroll
    for (int k = 0; k < OPT; k++) {
        int p = pbase + k*TPC;
        outb[(size_t)co*OHW*OHW + (size_t)(ty0+p/TILE)*OHW + tx0 + p%TILE] = fmaxf(acc[k], 0.f);
    }
}

// ============== conv1: fused bilinear 1024->256 downsample + 3x3 s2 conv ======
__global__ void __launch_bounds__(256) k_conv1(const float* __restrict__ im,
        const float* __restrict__ w, const float* __restrict__ bias) {
    constexpr int TILE = 8, IT = 17, NT = 16;
    constexpr int TPC = 32, OPT = 2;
    __shared__ float s_in[IT*IT*4];
    int bb = blockIdx.y;
    int tile = blockIdx.x;
    int ty0 = (tile/NT)*TILE, tx0 = (tile%NT)*TILE;
    int t = threadIdx.x;
    const float* imb = im + (size_t)bb * 3 * 1048576;
    for (int k = t; k < 289*3; k += 256) {
        int ci = k / 289, i = k % 289;
        int iy = 2*ty0 - 1 + i/IT;
        int ix = 2*tx0 - 1 + i%IT;
        float v = 0.f;
        if (iy >= 0 && iy < 256 && ix >= 0 && ix < 256) {
            const float* p = imb + (size_t)ci*1048576 + (size_t)(4*iy+1)*1024 + (4*ix+1);
            v = 0.25f*(__ldg(p) + __ldg(p+1) + __ldg(p+1024) + __ldg(p+1025));
        }
        s_in[i*4 + ci] = v;
    }
    __syncthreads();
    int co = t / TPC;
    int pbase = t % TPC;
    float acc[OPT];
    #pragma unroll
    for (int k = 0; k < OPT; k++) acc[k] = bias[co];
    const float* wc = w + co*3*9;
    float4 wk[9];
    #pragma unroll
    for (int k = 0; k < 9; k++) {
        wk[k].x = wc[0*9+k]; wk[k].y = wc[1*9+k]; wk[k].z = wc[2*9+k]; wk[k].w = 0.f;
    }
    #pragma unroll
    for (int k = 0; k < OPT; k++) {
        int p = pbase + k*TPC;
        int py = p/TILE, px = p%TILE;
        #pragma unroll
        for (int ky = 0; ky < 3; ky++)
        #pragma unroll
        for (int kx = 0; kx < 3; kx++) {
            float4 v = *(const float4*)&s_in[((2*py+ky)*IT + 2*px+kx)*4];
            float4 wv = wk[ky*3+kx];
            acc[k] += v.x*wv.x + v.y*wv.y + v.z*wv.z;
        }
    }
    float* outb = g_x1 + (size_t)bb*8*128*128;
    #pragma unroll
    for (int k = 0; k < OPT; k++) {
        int p = pbase + k*TPC;
        outb[(size_t)co*16384 + (size_t)(ty0+p/TILE)*128 + tx0 + p%TILE] = fmaxf(acc[k], 0.f);
    }
}

// ============== conv2 standalone ==============================================
__global__ void __launch_bounds__(256) k_conv2(const float* __restrict__ w,
                                               const float* __restrict__ b) {
    __shared__ float s_in[289*12];
    conv_run<8, 12, 16, 16, 128, 64, 8>(g_x1, w, b, g_x2, s_in,
                                        blockIdx.y, blockIdx.x, 0);
}

// ============== k_net: conv3 + conv4 + splat/local + global + coeff ===========
__global__ void __launch_bounds__(256) k_net(
        const float* __restrict__ sw2, const float* __restrict__ sb2,
        const float* __restrict__ sw3, const float* __restrict__ sb3,
        const float* __restrict__ spw, const float* __restrict__ spb,
        const float* __restrict__ val,
        const float* __restrict__ lw1, const float* __restrict__ lb1,
        const float* __restrict__ lw2, const float* __restrict__ lb2,
        const float* __restrict__ lw3, const float* __restrict__ lb3,
        const float* __restrict__ cw,  const float* __restrict__ cb,
        const float* __restrict__ fw1, const float* __restrict__ fb1,
        const float* __restrict__ fw2, const float* __restrict__ fb2,
        const float* __restrict__ gw,  const float* __restrict__ gb) {
    __shared__ float s_in[289*36];     // 41.6 KB, reused by every stage
    int bid = blockIdx.x;
    int t = threadIdx.x;

    // ---- S0: conv3  (16x64x64 -> 32x32x32), 16 tiles/batch ----
    conv_run<16, 20, 32, 32, 64, 32, 8>(g_x2, sw2, sb2, g_x3, s_in,
                                        bid >> 4, bid & 15, 0);
    gbar64();

    // ---- S1: conv4  (32x32x32 -> 64x16x16), 4 tiles x 4 co-groups/batch ----
    conv_run<32, 36, 16, 64, 32, 16, 8>(g_x3, sw3, sb3, g_x4, s_in,
                                        bid >> 4, (bid & 15) & 3, (bid & 15) >> 2);
    gbar64();

    // ---- S2: splat + local 3-layer MLP, 16 positions/block ----
    {
        int bb = bid >> 4;
        int pos0 = (bid & 15) * 16;
        float* A  = s_in;           // 64x16
        float* Bf = s_in + 1024;    // 128x16
        float* Cf = s_in + 3072;    // 128x16
        const float* x4 = g_x4 + bb*16384;
        float vb = val[bb];
        for (int o = t; o < 1024; o += 256) {
            int ch = o >> 4, p = o & 15;
            float acc = spb[ch] + vb;
            const float* wr = spw + ch*64;
            #pragma unroll 8
            for (int i = 0; i < 64; i++) acc = fmaf(wr[i], x4[i*256 + pos0 + p], acc);
            A[ch*16 + p] = acc;
            g_splat[(bb*64 + ch)*256 + pos0 + p] = acc;
        }
        __syncthreads();
        for (int o = t; o < 2048; o += 256) {
            int ch = o >> 4, p = o & 15;
            float acc = lb1[ch];
            const float* wr = lw1 + ch*64;
            #pragma unroll 8
            for (int i = 0; i < 64; i++) acc = fmaf(wr[i], A[i*16 + p], acc);
            Bf[ch*16 + p] = fmaxf(acc, 0.f);
        }
        __syncthreads();
        for (int o = t; o < 2048; o += 256) {
            int ch = o >> 4, p = o & 15;
            float acc = lb2[ch];
            const float* wr = lw2 + ch*128;
            #pragma unroll 8
            for (int i = 0; i < 128; i++) acc = fmaf(wr[i], Bf[i*16 + p], acc);
            Cf[ch*16 + p] = fmaxf(acc, 0.f);
        }
        __syncthreads();
        for (int o = t; o < 1024; o += 256) {
            int ch = o >> 4, p = o & 15;
            float acc = lb3[ch];
            const float* wr = lw3 + ch*128;
            #pragma unroll 8
            for (int i = 0; i < 128; i++) acc = fmaf(wr[i], Cf[i*16 + p], acc);
            g_l3[(bb*64 + ch)*256 + pos0 + p] = fmaxf(acc, 0.f);
        }
    }
    gbar64();

    // ---- S3: global path (blocks 0..3, one per batch) ----
    if (bid < 4) {
        int bb = bid;
        float* c4 = s_in;          // 4x64
        float* cp = s_in + 256;    // 64
        float* f1 = s_in + 320;    // 64
        const float* sp = g_splat + bb*64*256;
        int oc = t >> 6, idx = t & 63;
        int gy2 = idx >> 3, gx2 = idx & 7;
        int pos = (2*gy2)*16 + 2*gx2;
        float acc = cb[oc];
        for (int i = 0; i < 64; i++) acc = fmaf(cw[oc*64+i], sp[i*256+pos], acc);
        c4[oc*64 + idx] = fmaxf(acc, 0.f);
        __syncthreads();
        if (t < 64) {
            int oc2 = t >> 4, py = (t >> 2) & 3, px = t & 3;
            cp[t] = 0.25f*(c4[oc2*64 + (2*py)*8 + 2*px]   + c4[oc2*64 + (2*py)*8 + 2*px+1] +
                           c4[oc2*64 + (2*py+1)*8 + 2*px] + c4[oc2*64 + (2*py+1)*8 + 2*px+1]);
        }
        __syncthreads();
        if (t < 64) {
            float a2 = fb1[t];
            for (int i = 0; i < 64; i++) a2 = fmaf(fw1[t*64+i], cp[i], a2);
            f1[t] = fmaxf(a2, 0.f);
        }
        __syncthreads();
        if (t < 64) {
            float a2 = fb2[t];
            for (int i = 0; i < 64; i++) a2 = fmaf(fw2[t*64+i], f1[i], a2);
            g_cvec[bb*64 + t] = fmaxf(a2, 0.f);
        }
    }
    gbar64();

    // ---- S4: fused = relu(c + loc); coeff pw 64->96; write grid ----
    {
        int bb = bid >> 4;
        int tl = bid & 15;
        float* fused = s_in;       // [64][17]
        const float* l3p = g_l3 + bb*64*256;
        const float* cv = g_cvec + bb*64;
        for (int o = t; o < 1024; o += 256) {
            int ch = o >> 4, p = o & 15;
            fused[ch*17 + p] = fmaxf(cv[ch] + l3p[ch*256 + tl*16 + p], 0.f);
        }
        __syncthreads();
        for (int o = t; o < 1536; o += 256) {
            int och = o >> 4, p = o & 15;
            float acc = gb[och];
            const float* wr = gw + och*64;
            #pragma unroll 8
            for (int i = 0; i < 64; i++) acc = fmaf(wr[i], fused[i*17 + p], acc);
            int lb = och / 12, cc = och % 12;
            g_grid[((bb*12 + cc)*8 + lb)*256 + tl*16 + p] = acc;
        }
    }
}

// ============== fused guide + bilateral slice =================================
__global__ void __launch_bounds__(256) k_slice(
        const float* __restrict__ im,
        const float* __restrict__ ccm_w, const float* __restrict__ ccm_b,
        const float* __restrict__ shifts, const float* __restrict__ slopes,
        const float* __restrict__ prw, const float* __restrict__ prb,
        float* __restrict__ out) {
    int bx = blockIdx.x, by = blockIdx.y, bb = blockIdx.z;
    __shared__ float sg[864];               // [cell(j*3+k)][z][c12]
    __shared__ float gy[4*72*4];            // per-group y-interp table
    __shared__ float s_ccm[9], s_ccmb[3], s_prw[3], s_prb[1];
    __shared__ float s_sh[48];
    __shared__ float s_cs[3][17], s_csh[3][17];
    int t = threadIdx.x;

    const float* gr = g_grid + (size_t)bb * 12 * 8 * 256;
    for (int k = t; k < 864; k += 256) {
        int c = k % 12;
        int z = (k / 12) % 8;
        int cell = k / 96;
        int j = cell / 3, kx = cell % 3;
        int yi = min(max(by - 1 + j, 0), 15);
        int xi = min(max(bx - 1 + kx, 0), 15);
        sg[k] = gr[(c*8 + z)*256 + yi*16 + xi];
    }
    if (t < 9)               s_ccm[t] = ccm_w[t];
    if (t >= 16 && t < 19)   s_ccmb[t-16] = ccm_b[t-16];
    if (t >= 32 && t < 80)   s_sh[t-32] = shifts[t-32];
    if (t >= 96 && t < 99)   s_prw[t-96] = prw[t-96];
    if (t == 102)            s_prb[0] = prb[0];
    if (t >= 104 && t < 107) {
        int c = t - 104;
        float cs = 0.f, csh = 0.f;
        s_cs[c][0] = 0.f; s_csh[c][0] = 0.f;
        #pragma unroll
        for (int k = 0; k < 16; k++) {
            float s = slopes[c*16+k], h = shifts[c*16+k];
            cs += s; csh += s*h;
            s_cs[c][k+1] = cs; s_csh[c][k+1] = csh;
        }
    }
    __syncthreads();

    int g = t >> 6;
    int lx = t & 63;
    int x = bx*64 + lx;
    float cxv = ((float)x + 0.5f) * (1.0f/64.0f) - 0.5f;
    float wx = cxv - floorf(cxv);
    int k0 = (int)floorf(cxv) - (bx - 1);
    const float* imb = im + (size_t)bb * 3 * 1048576;
    float* outb = out + (size_t)bb * 3 * 1048576;

    for (int r = 0; r < 16; r++) {
        int y = by*64 + g + 4*r;
        float cyv = ((float)y + 0.5f) * (1.0f/64.0f) - 0.5f;
        float wy = cyv - floorf(cyv);
        int j0 = (int)floorf(cyv) - (by - 1);

        for (int e = lx; e < 72; e += 64) {
            int cellx = e / 24;
            int z = (e / 3) % 8;
            int v = e % 3;
            float4 a = ((const float4*)sg)[((j0*3 + cellx)*8 + z)*3 + v];
            float4 b4 = ((const float4*)sg)[(((j0+1)*3 + cellx)*8 + z)*3 + v];
            float4 res;
            res.x = fmaf(wy, b4.x - a.x, a.x);
            res.y = fmaf(wy, b4.y - a.y, a.y);
            res.z = fmaf(wy, b4.z - a.z, a.z);
            res.w = fmaf(wy, b4.w - a.w, a.w);
            ((float4*)gy)[g*72 + e] = res;
        }
        asm volatile("bar.sync %0, %1;" :: "r"(g+1), "r"(64) : "memory");

        size_t poff = (size_t)y * 1024 + x;
        float i0 = __ldg(&imb[poff]);
        float i1 = __ldg(&imb[poff + 1048576]);
        float i2 = __ldg(&imb[poff + 2097152]);

        float q0 = s_ccmb[0] + s_ccm[0]*i0 + s_ccm[1]*i1 + s_ccm[2]*i2;
        float q1 = s_ccmb[1] + s_ccm[3]*i0 + s_ccm[4]*i1 + s_ccm[5]*i2;
        float q2 = s_ccmb[2] + s_ccm[6]*i0 + s_ccm[7]*i1 + s_ccm[8]*i2;
        float tt[3];
        float qv[3] = {q0, q1, q2};
        #pragma unroll
        for (int c = 0; c < 3; c++) {
            const float* H = &s_sh[c*16];
            float gv = qv[c];
            int p = (gv > H[7]) ? 8 : 0;
            p += (gv > H[p+3]) ? 4 : 0;
            p += (gv > H[p+1]) ? 2 : 0;
            p += (gv > H[p])   ? 1 : 0;
            p += (gv > H[p])   ? 1 : 0;
            tt[c] = fmaf(gv, s_cs[c][p], -s_csh[c][p]);
        }
        float gg = s_prb[0] + s_prw[0]*tt[0] + s_prw[1]*tt[1] + s_prw[2]*tt[2];
        float guide = fminf(fmaxf(gg, 0.f), 1.f);

        float cz = guide * 8.0f - 0.5f;
        float z0f = floorf(cz);
        float wz = cz - z0f;
        int z0 = (int)z0f;
        int zi0 = min(max(z0, 0), 7);
        int zi1 = min(max(z0 + 1, 0), 7);

        float w00 = (1.f-wx)*(1.f-wz), w01 = (1.f-wx)*wz;
        float w10 = wx*(1.f-wz),       w11 = wx*wz;

        const float4* T = (const float4*)gy;
        int bA = (g*3 + k0)*8;
        int bB = bA + 8;
        int iA0 = (bA + zi0)*3, iA1 = (bA + zi1)*3;
        int iB0 = (bB + zi0)*3, iB1 = (bB + zi1)*3;

        float a0,a1,a2,a3,a4,a5,a6,a7,a8,a9,a10,a11;
        {
            float4 v0 = T[iA0], v1 = T[iA1], v2 = T[iB0], v3 = T[iB1];
            a0 = w00*v0.x + w01*v1.x + w10*v2.x + w11*v3.x;
            a1 = w00*v0.y + w01*v1.y + w10*v2.y + w11*v3.y;
            a2 = w00*v0.z + w01*v1.z + w10*v2.z + w11*v3.z;
            a3 = w00*v0.w + w01*v1.w + w10*v2.w + w11*v3.w;
        }
        {
            float4 v0 = T[iA0+1], v1 = T[iA1+1], v2 = T[iB0+1], v3 = T[iB1+1];
            a4 = w00*v0.x + w01*v1.x + w10*v2.x + w11*v3.x;
            a5 = w00*v0.y + w01*v1.y + w10*v2.y + w11*v3.y;
            a6 = w00*v0.z + w01*v1.z + w10*v2.z + w11*v3.z;
            a7 = w00*v0.w + w01*v1.w + w10*v2.w + w11*v3.w;
        }
        {
            float4 v0 = T[iA0+2], v1 = T[iA1+2], v2 = T[iB0+2], v3 = T[iB1+2];
            a8  = w00*v0.x + w01*v1.x + w10*v2.x + w11*v3.x;
            a9  = w00*v0.y + w01*v1.y + w10*v2.y + w11*v3.y;
            a10 = w00*v0.z + w01*v1.z + w10*v2.z + w11*v3.z;
            a11 = w00*v0.w + w01*v1.w + w10*v2.w + w11*v3.w;
        }
        outb[poff]           = fmaf(a0, i0, fmaf(a1, i1, fmaf(a2,  i2, a3)));
        outb[poff + 1048576] = fmaf(a4, i0, fmaf(a5, i1, fmaf(a6,  i2, a7)));
        outb[poff + 2097152] = fmaf(a8, i0, fmaf(a9, i1, fmaf(a10, i2, a11)));

        asm volatile("bar.sync %0, %1;" :: "r"(g+1), "r"(64) : "memory");
    }
}

// ---------------- launcher ---------------------------------------------------
extern "C" void kernel_launch(void* const* d_in, const int* in_sizes, int n_in,
                              void* d_out, int out_size) {
    const float* image = (const float*)d_in[0];
    const float* val   = (const float*)d_in[1];
    const float* sw0 = (const float*)d_in[2];  const float* sb0 = (const float*)d_in[3];
    const float* sw1 = (const float*)d_in[4];  const float* sb1 = (const float*)d_in[5];
    const float* sw2 = (const float*)d_in[6];  const float* sb2 = (const float*)d_in[7];
    const float* sw3 = (const float*)d_in[8];  const float* sb3 = (const float*)d_in[9];
    const float* spw = (const float*)d_in[10]; const float* spb = (const float*)d_in[11];
    const float* lw1 = (const float*)d_in[12]; const float* lb1 = (const float*)d_in[13];
    const float* lw2 = (const float*)d_in[14]; const float* lb2 = (const float*)d_in[15];
    const float* lw3 = (const float*)d_in[16]; const float* lb3 = (const float*)d_in[17];
    const float* cw  = (const float*)d_in[18]; const float* cb  = (const float*)d_in[19];
    const float* fw1 = (const float*)d_in[20]; const float* fb1 = (const float*)d_in[21];
    const float* fw2 = (const float*)d_in[22]; const float* fb2 = (const float*)d_in[23];
    const float* gw  = (const float*)d_in[24]; const float* gb  = (const float*)d_in[25];
    const float* ccm_w = (const float*)d_in[26]; const float* ccm_b = (const float*)d_in[27];
    const float* shifts = (const float*)d_in[28];
    const float* slopes = (const float*)d_in[29];
    const float* prw = (const float*)d_in[30]; const float* prb = (const float*)d_in[31];
    float* out = (float*)d_out;

    k_conv1<<<dim3(256, 4), 256>>>(image, sw0, sb0);
    k_conv2<<<dim3(64, 4), 256>>>(sw1, sb1);
    k_net<<<64, 256>>>(sw2, sb2, sw3, sb3, spw, spb, val,
                       lw1, lb1, lw2, lb2, lw3, lb3,
                       cw, cb, fw1, fb1, fw2, fb2, gw, gb);
    k_slice<<<dim3(16, 16, 4), 256>>>(image, ccm_w, ccm_b, shifts, slopes, prw, prb, out);
}